// round 5
// baseline (speedup 1.0000x reference)
#include <cuda_runtime.h>
#include <cstdint>

#define IN_FEAT 3072
#define PADDED  4096
#define M_ROWS  8192
#define N_COLS  4096
#define K_DIM   4096

#define BM 128
#define BN 128
#define BK 64
#define NSTAGE 4
#define NITER (K_DIM / BK)

#define A_STAGE 8192              // 128 rows x 64 B
#define B_STAGE 8192
#define SMEM_A_OFF 0
#define SMEM_B_OFF (NSTAGE * A_STAGE)
#define SMEM_TOTAL (NSTAGE * (A_STAGE + B_STAGE))   // 65536

// -------- device scratch (static globals: no allocations allowed) ----------
__device__ int8_t g_zx[(size_t)M_ROWS * K_DIM];   // 32 MB
__device__ int8_t g_zw[(size_t)N_COLS * K_DIM];   // 16 MB
__device__ float  g_alpha[M_ROWS];
__device__ float  g_beta[N_COLS];

// -------- helpers -----------------------------------------------------------
__device__ __forceinline__ uint32_t smem_u32(const void* p) {
    uint32_t a;
    asm("{ .reg .u64 t; cvta.to.shared.u64 t, %1; cvt.u32.u64 %0, t; }"
        : "=r"(a) : "l"(p));
    return a;
}

__device__ __forceinline__ void cpa16(uint32_t sdst, const void* gsrc) {
    asm volatile("cp.async.cg.shared.global [%0], [%1], 16;" :: "r"(sdst), "l"(gsrc));
}

__device__ __forceinline__ void ldm4(uint32_t addr, uint32_t& r0, uint32_t& r1,
                                     uint32_t& r2, uint32_t& r3) {
    asm volatile("ldmatrix.sync.aligned.m8n8.x4.shared.b16 {%0,%1,%2,%3}, [%4];"
                 : "=r"(r0), "=r"(r1), "=r"(r2), "=r"(r3) : "r"(addr));
}

__device__ __forceinline__ void mma_s8(int* d, const uint32_t* a, uint32_t b0, uint32_t b1) {
    asm volatile(
        "mma.sync.aligned.m16n8k32.row.col.s32.s8.s8.s32 "
        "{%0,%1,%2,%3}, {%4,%5,%6,%7}, {%8,%9}, {%0,%1,%2,%3};"
        : "+r"(d[0]), "+r"(d[1]), "+r"(d[2]), "+r"(d[3])
        : "r"(a[0]), "r"(a[1]), "r"(a[2]), "r"(a[3]), "r"(b0), "r"(b1));
}

// swizzle for 64-byte rows at 16B-granule granularity:
// granule (row, c) -> byte row*64 + ((c ^ ((row>>1)&3)) * 16)
// conflict-free for cp.async 16B stores and all ldmatrix 8-lane phases.
#define SWZ64(row, c) (((uint32_t)(row) << 6) + ((((c) ^ (((row) >> 1) & 3)) & 3) << 4))

// ============================================================================
// Kernel 1: per-row pad -> FWHT(4096) -> quantize (z = q-128, int8) -> row sum
// blocks [0, M_ROWS): x rows -> g_zx/g_alpha; [M_ROWS, +N_COLS): w -> g_zw/g_beta
// ============================================================================
__global__ void __launch_bounds__(256)
hq_fwht_quant(const float* __restrict__ x, const float* __restrict__ w,
              const float* __restrict__ bias, float kA, float c2) {
    __shared__ float xch[PADDED];
    __shared__ float wsum[8];

    int row = blockIdx.x;
    int mode = (row >= M_ROWS);
    if (mode) row -= M_ROWS;
    const float* in = mode ? (w + (size_t)row * IN_FEAT) : (x + (size_t)row * IN_FEAT);
    const int t = threadIdx.x;

    float v[16];
    if (t < IN_FEAT / 16) {
        const float4* p = (const float4*)(in + t * 16);
        float4 a0 = p[0], a1 = p[1], a2 = p[2], a3 = p[3];
        v[0]=a0.x; v[1]=a0.y; v[2]=a0.z; v[3]=a0.w;
        v[4]=a1.x; v[5]=a1.y; v[6]=a1.z; v[7]=a1.w;
        v[8]=a2.x; v[9]=a2.y; v[10]=a2.z; v[11]=a2.w;
        v[12]=a3.x; v[13]=a3.y; v[14]=a3.z; v[15]=a3.w;
    } else {
        #pragma unroll
        for (int e = 0; e < 16; ++e) v[e] = 0.0f;
    }

    // strides 1,2,4,8 in registers (element index bits 0..3)
    #pragma unroll
    for (int st = 1; st < 16; st <<= 1) {
        #pragma unroll
        for (int e = 0; e < 16; ++e)
            if (!(e & st)) {
                float a = v[e], b = v[e | st];
                v[e] = a + b;
                v[e | st] = a - b;
            }
    }
    // strides 16..256 via shfl_xor (thread bits 0..4)
    #pragma unroll
    for (int b = 1; b <= 16; b <<= 1) {
        bool up = (t & b) != 0;
        #pragma unroll
        for (int e = 0; e < 16; ++e) {
            float o = __shfl_xor_sync(0xffffffffu, v[e], b, 32);
            v[e] = up ? (o - v[e]) : (v[e] + o);
        }
    }
    // strides 512,1024,2048 via smem (thread bits 5..7)
    #pragma unroll
    for (int b = 32; b <= 128; b <<= 1) {
        __syncthreads();
        #pragma unroll
        for (int e = 0; e < 16; ++e) xch[e * 256 + t] = v[e];
        __syncthreads();
        int pt = t ^ b;
        bool up = (t & b) != 0;
        #pragma unroll
        for (int e = 0; e < 16; ++e) {
            float o = xch[e * 256 + pt];
            v[e] = up ? (o - v[e]) : (v[e] + o);
        }
    }

    // quantize: q = clip(rint((clip(v,-384,384)+384)/scale),0,255); z = q-128
    const float inv_qs = 255.0f / 768.0f;
    int zi[16];
    float zsum = 0.0f;
    #pragma unroll
    for (int e = 0; e < 16; ++e) {
        float u = fminf(fmaxf(v[e], -384.0f), 384.0f);
        float q = fminf(fmaxf(rintf((u + 384.0f) * inv_qs), 0.0f), 255.0f);
        zi[e] = (int)q - 128;
        zsum += (float)zi[e];
    }
    uint32_t pk[4];
    #pragma unroll
    for (int j = 0; j < 4; ++j)
        pk[j] = (uint32_t)(zi[4*j] & 0xff) | ((uint32_t)(zi[4*j+1] & 0xff) << 8) |
                ((uint32_t)(zi[4*j+2] & 0xff) << 16) | ((uint32_t)(zi[4*j+3] & 0xff) << 24);
    int8_t* oz = (mode ? g_zw : g_zx) + (size_t)row * PADDED + t * 16;
    *(uint4*)oz = make_uint4(pk[0], pk[1], pk[2], pk[3]);

    #pragma unroll
    for (int off = 16; off > 0; off >>= 1)
        zsum += __shfl_down_sync(0xffffffffu, zsum, off, 32);
    if ((t & 31) == 0) wsum[t >> 5] = zsum;
    __syncthreads();
    if (t == 0) {
        float S = 0.0f;
        #pragma unroll
        for (int i = 0; i < 8; ++i) S += wsum[i];
        float stat = kA * S;
        if (mode) g_beta[row] = stat + c2 + bias[row];
        else      g_alpha[row] = stat;
    }
}

// ============================================================================
// Kernel 2: int8 mma.sync GEMM, tile 128x128, BK=64, 4-stage cp.async pipeline
// 8 warps: warpM = wid&3 (32 rows each), warpN = wid>>2 (64 cols each)
// ============================================================================
__device__ __forceinline__ void load_chunk(uint32_t sb, const int8_t* Ag, const int8_t* Bg,
                                           int k0, int s, int tid) {
    uint32_t aS = sb + SMEM_A_OFF + s * A_STAGE;
    uint32_t bS = sb + SMEM_B_OFF + s * B_STAGE;
    #pragma unroll
    for (int j = 0; j < 2; ++j) {
        int seg = tid + 256 * j;
        int r = seg >> 2, c = seg & 3;
        cpa16(aS + SWZ64(r, c), Ag + (size_t)r * K_DIM + k0 + c * 16);
        cpa16(bS + SWZ64(r, c), Bg + (size_t)r * K_DIM + k0 + c * 16);
    }
}

__global__ void __launch_bounds__(256, 2)
hq_gemm(float* __restrict__ out, float k1) {
    extern __shared__ char smem[];
    const uint32_t sb = smem_u32(smem);
    const int tid = threadIdx.x;
    const int wid = tid >> 5, lane = tid & 31;
    const int warpM = wid & 3, warpN = wid >> 2;

    const int m0 = blockIdx.y * BM;
    const int n0 = blockIdx.x * BN;
    const int8_t* Ag = g_zx + (size_t)m0 * K_DIM;
    const int8_t* Bg = g_zw + (size_t)n0 * K_DIM;

    // per-thread ldmatrix address components (see fragment-layout derivation)
    const int arow = warpM * 32 + (lane & 7) + ((lane >> 3) & 1) * 8;
    const int acadd = (lane >> 4) & 1;
    const int axor = (arow >> 1) & 3;
    const int brow = warpN * 64 + (lane & 7) + ((lane >> 4) & 1) * 8;
    const int bcadd = (lane >> 3) & 1;
    const int bxor = (brow >> 1) & 3;

    int acc[64];
    #pragma unroll
    for (int i = 0; i < 64; ++i) acc[i] = 0;

    #pragma unroll
    for (int i = 0; i < NSTAGE - 1; ++i) {
        load_chunk(sb, Ag, Bg, i * BK, i, tid);
        asm volatile("cp.async.commit_group;" ::: "memory");
    }

    for (int c = 0; c < NITER; ++c) {
        asm volatile("cp.async.wait_group 2;" ::: "memory");
        __syncthreads();  // chunk c resident; all warps done with stage (c-1)&3

        if (c + NSTAGE - 1 < NITER)
            load_chunk(sb, Ag, Bg, (c + NSTAGE - 1) * BK, (c + NSTAGE - 1) & (NSTAGE - 1), tid);
        asm volatile("cp.async.commit_group;" ::: "memory");

        uint32_t aS = sb + SMEM_A_OFF + (c & (NSTAGE - 1)) * A_STAGE;
        uint32_t bS = sb + SMEM_B_OFF + (c & (NSTAGE - 1)) * B_STAGE;
        #pragma unroll
        for (int kk = 0; kk < 2; ++kk) {
            uint32_t af[8], bf[16];
            #pragma unroll
            for (int ma = 0; ma < 2; ++ma)
                ldm4(aS + (uint32_t)(arow + ma * 16) * 64 +
                         (uint32_t)(((2 * kk + acadd) ^ axor) << 4),
                     af[4*ma], af[4*ma+1], af[4*ma+2], af[4*ma+3]);
            #pragma unroll
            for (int nb = 0; nb < 4; ++nb)
                ldm4(bS + (uint32_t)(brow + nb * 16) * 64 +
                         (uint32_t)(((2 * kk + bcadd) ^ bxor) << 4),
                     bf[4*nb], bf[4*nb+1], bf[4*nb+2], bf[4*nb+3]);
            #pragma unroll
            for (int ma = 0; ma < 2; ++ma)
                #pragma unroll
                for (int na = 0; na < 8; ++na)
                    mma_s8(acc + (ma * 8 + na) * 4, af + 4 * ma,
                           bf[(na >> 1) * 4 + (na & 1) * 2],
                           bf[(na >> 1) * 4 + (na & 1) * 2 + 1]);
        }
    }

    // epilogue: out = k1*acc + alpha[row] + beta[col]
    #pragma unroll
    for (int ma = 0; ma < 2; ++ma) {
        int r0 = m0 + warpM * 32 + ma * 16 + (lane >> 2);
        float al0 = g_alpha[r0], al1 = g_alpha[r0 + 8];
        float* o0 = out + (size_t)r0 * N_COLS;
        float* o1 = out + (size_t)(r0 + 8) * N_COLS;
        #pragma unroll
        for (int na = 0; na < 8; ++na) {
            int col = n0 + warpN * 64 + na * 8 + (lane & 3) * 2;
            float b0 = g_beta[col], b1 = g_beta[col + 1];
            const int* d = acc + (ma * 8 + na) * 4;
            float2 p0, p1;
            p0.x = fmaf(k1, (float)d[0], al0 + b0);
            p0.y = fmaf(k1, (float)d[1], al0 + b1);
            p1.x = fmaf(k1, (float)d[2], al1 + b0);
            p1.y = fmaf(k1, (float)d[3], al1 + b1);
            *(float2*)(o0 + col) = p0;
            *(float2*)(o1 + col) = p1;
        }
    }
}

// ============================================================================
extern "C" void kernel_launch(void* const* d_in, const int* in_sizes, int n_in,
                              void* d_out, int out_size) {
    const float* x = (const float*)d_in[0];
    const float* w = (const float*)d_in[1];
    const float* bias = (const float*)d_in[2];
    float* out = (float*)d_out;

    const float scale = 768.0f / 255.0f;
    const float cc = -384.0f + 128.0f * scale;        // = 384/255
    const float k1 = scale * scale / (float)PADDED;
    const float kA = scale * cc / (float)PADDED;
    const float c2 = cc * cc;

    hq_fwht_quant<<<M_ROWS + N_COLS, 256>>>(x, w, bias, kA, c2);

    static_assert(SMEM_TOTAL == 65536, "smem");
    cudaFuncSetAttribute(hq_gemm, cudaFuncAttributeMaxDynamicSharedMemorySize, SMEM_TOTAL);
    dim3 grid(N_COLS / BN, M_ROWS / BM);
    hq_gemm<<<grid, 256, SMEM_TOTAL>>>(out, k1);
}